// round 2
// baseline (speedup 1.0000x reference)
#include <cuda_runtime.h>

// Problem constants (fixed by setup_inputs)
#define TT 32768      // B*S tokens
#define SS 8192       // sequence length
#define DD 512        // model dim
#define FF 2048       // ffn hidden
#define NM 1024       // concatenated MoE hidden (2 layers * E*H=512)

// Scratch (device globals; no allocation allowed)
__device__ float g_H1[(unsigned long long)TT * FF];   // ffn hidden, 268 MB
__device__ float g_Hm[(unsigned long long)TT * NM];   // moe hidden (both layers), 134 MB
__device__ float g_WaT[DD * NM];                      // Wa1|Wa2 transposed to [D, 1024]
__device__ float g_Wbcat[NM * DD];                    // Wb1;Wb2 stacked [1024, D]
__device__ float g_w[TT * 16];                        // dense gate weights, 8 per layer

__device__ __forceinline__ float gelu_f(float x) {
    // tanh-approx gelu (jax.nn.gelu default approximate=True)
    float x3 = x * x * x;
    float t = tanhf(0.7978845608028654f * (x + 0.044715f * x3));
    return 0.5f * x * (1.0f + t);
}

// ---------------------------------------------------------------------------
// Prep: build WaT [D, 1024] (column n = L*512 + e*64 + h from Wa_L[e,d,h])
//       and Wbcat [1024, D] (rows 0..511 = Wb1 flat, 512..1023 = Wb2 flat)
// ---------------------------------------------------------------------------
__global__ void prep_kernel(const float* __restrict__ Wa1, const float* __restrict__ Wa2,
                            const float* __restrict__ Wb1, const float* __restrict__ Wb2) {
    int i = blockIdx.x * 256 + threadIdx.x;           // 0 .. 524287
    if (i >= DD * NM) return;
    int d = i >> 10, n = i & 1023;
    int L = n >> 9, c = n & 511;
    const float* Wa = L ? Wa2 : Wa1;
    g_WaT[i] = Wa[((c >> 6) * DD + d) * 64 + (c & 63)];
    // Wbcat is a straight copy
    g_Wbcat[i] = (i < (NM * DD / 2)) ? Wb1[i] : Wb2[i - (NM * DD / 2)];
}

// ---------------------------------------------------------------------------
// Gating: one warp per token; computes dense top-2 softmax weights for both
// MoE layers into g_w[t*16 + {0..7 layer1, 8..15 layer2}]
// ---------------------------------------------------------------------------
__device__ __forceinline__ void write_top2(const float* a, float* o) {
    int i0 = 0; float v0 = a[0];
#pragma unroll
    for (int e = 1; e < 8; e++) if (a[e] > v0) { v0 = a[e]; i0 = e; }
    int i1 = -1; float v1 = -3.4e38f;
#pragma unroll
    for (int e = 0; e < 8; e++) if (e != i0 && a[e] > v1) { v1 = a[e]; i1 = e; }
    float t = expf(v1 - v0);
    float inv = 1.0f / (1.0f + t);
#pragma unroll
    for (int e = 0; e < 8; e++) o[e] = 0.0f;
    o[i0] = inv;
    o[i1] = t * inv;
}

__global__ void gate_kernel(const float* __restrict__ x,
                            const float* __restrict__ Wg1,
                            const float* __restrict__ Wg2) {
    int tok = blockIdx.x * 8 + (threadIdx.x >> 5);
    int lane = threadIdx.x & 31;
    if (tok >= TT) return;
    const float* xr = x + (size_t)tok * DD;
    float a1[8], a2[8];
#pragma unroll
    for (int e = 0; e < 8; e++) { a1[e] = 0.0f; a2[e] = 0.0f; }
    for (int j = lane; j < DD; j += 32) {
        float xv = xr[j];
#pragma unroll
        for (int e = 0; e < 8; e++) {
            a1[e] = fmaf(xv, Wg1[j * 8 + e], a1[e]);
            a2[e] = fmaf(xv, Wg2[j * 8 + e], a2[e]);
        }
    }
#pragma unroll
    for (int e = 0; e < 8; e++) {
#pragma unroll
        for (int o = 16; o; o >>= 1) {
            a1[e] += __shfl_xor_sync(0xffffffffu, a1[e], o);
            a2[e] += __shfl_xor_sync(0xffffffffu, a2[e], o);
        }
    }
    if (lane == 0) {
        write_top2(a1, &g_w[tok * 16]);
        write_top2(a2, &g_w[tok * 16 + 8]);
    }
}

// ---------------------------------------------------------------------------
// SGEMM 128x128x8, 256 threads, 8x8 register tile.
// EPI 0: C = gelu(A*B + bias)          (ffn1 -> g_H1)
// EPI 1: C = A*B + bias                (ffn2 -> out)
// EPI 2: C = mask * w[t,e] * gelu(A*B) (moe up -> g_Hm), early-exit masked tiles
// EPI 3: C += A*B  (rows with s>=id)   (moe down -> out), early-exit masked tiles
// ---------------------------------------------------------------------------
template <int EPI>
__global__ __launch_bounds__(256, 2)
void gemm_kernel(const float* __restrict__ A, const float* __restrict__ Bm,
                 const float* __restrict__ bias, float* __restrict__ C,
                 int M, int N, int K, const int* __restrict__ idp) {
    const int col0 = blockIdx.x * 128;
    const int row0 = blockIdx.y * 128;
    int idv = 0;
    if (EPI >= 2) {
        idv = *idp;
        int s0 = row0 & (SS - 1);
        if (s0 + 127 < idv) return;   // whole tile below mask boundary: no MoE work
    }

    __shared__ float As[8][128];
    __shared__ float Bs[8][128];

    const int tid = threadIdx.x;
    const int tx = tid & 15;
    const int ty = tid >> 4;

    const int arow = tid >> 1;          // 0..127
    const int akk  = (tid & 1) * 4;     // 0 or 4
    const int brow = tid >> 5;          // 0..7
    const int bcol = (tid & 31) * 4;

    const float* Aptr = A + (size_t)(row0 + arow) * K + akk;
    const float* Bptr = Bm + (size_t)brow * N + col0 + bcol;

    float acc[8][8];
#pragma unroll
    for (int i = 0; i < 8; i++)
#pragma unroll
        for (int j = 0; j < 8; j++) acc[i][j] = 0.0f;

    for (int k0 = 0; k0 < K; k0 += 8) {
        float4 av = *(const float4*)(Aptr + k0);
        float4 bv = *(const float4*)(Bptr + (size_t)k0 * N);
        As[akk + 0][arow] = av.x;
        As[akk + 1][arow] = av.y;
        As[akk + 2][arow] = av.z;
        As[akk + 3][arow] = av.w;
        *(float4*)&Bs[brow][bcol] = bv;
        __syncthreads();
#pragma unroll
        for (int k = 0; k < 8; k++) {
            float4 a0 = *(const float4*)&As[k][ty * 8];
            float4 a1 = *(const float4*)&As[k][ty * 8 + 4];
            float4 b0 = *(const float4*)&Bs[k][tx * 8];
            float4 b1 = *(const float4*)&Bs[k][tx * 8 + 4];
            float ar[8] = {a0.x, a0.y, a0.z, a0.w, a1.x, a1.y, a1.z, a1.w};
            float br[8] = {b0.x, b0.y, b0.z, b0.w, b1.x, b1.y, b1.z, b1.w};
#pragma unroll
            for (int i = 0; i < 8; i++)
#pragma unroll
                for (int j = 0; j < 8; j++)
                    acc[i][j] = fmaf(ar[i], br[j], acc[i][j]);
        }
        __syncthreads();
    }

    // Epilogue
    float bv8[8];
    if (EPI == 0 || EPI == 1) {
#pragma unroll
        for (int j = 0; j < 8; j++) bv8[j] = bias[col0 + tx * 8 + j];
    }

#pragma unroll
    for (int i = 0; i < 8; i++) {
        int m = row0 + ty * 8 + i;
        int s = m & (SS - 1);
        float* crow = C + (size_t)m * N + col0 + tx * 8;
        if (EPI == 0) {
#pragma unroll
            for (int j = 0; j < 8; j++) crow[j] = gelu_f(acc[i][j] + bv8[j]);
        } else if (EPI == 1) {
#pragma unroll
            for (int j = 0; j < 8; j++) crow[j] = acc[i][j] + bv8[j];
        } else if (EPI == 2) {
            bool msk = (s >= idv);
            const float* wrow = &g_w[m * 16];
#pragma unroll
            for (int j = 0; j < 8; j++) {
                int n = col0 + tx * 8 + j;
                float wv = wrow[n >> 6];   // n/64 in [0,16): layer1 experts 0..7, layer2 8..15
                crow[j] = msk ? gelu_f(acc[i][j]) * wv : 0.0f;
            }
        } else {  // EPI == 3
            if (s >= idv) {
#pragma unroll
                for (int j = 0; j < 8; j++) crow[j] += acc[i][j];
            }
        }
    }
}

// ---------------------------------------------------------------------------
extern "C" void kernel_launch(void* const* d_in, const int* in_sizes, int n_in,
                              void* d_out, int out_size) {
    const float* x   = (const float*)d_in[0];
    const int*   idp = (const int*)  d_in[1];
    const float* W1  = (const float*)d_in[2];
    const float* b1  = (const float*)d_in[3];
    const float* W2  = (const float*)d_in[4];
    const float* b2  = (const float*)d_in[5];
    const float* Wg1 = (const float*)d_in[6];
    const float* Wa1 = (const float*)d_in[7];
    const float* Wb1 = (const float*)d_in[8]; (void)Wb1;
    const float* Wg2 = (const float*)d_in[9];
    const float* Wa2 = (const float*)d_in[10];
    const float* Wb2 = (const float*)d_in[11];
    float* out = (float*)d_out;
    (void)in_sizes; (void)n_in; (void)out_size;

    float *H1, *Hm, *WaT, *Wbcat;
    cudaGetSymbolAddress((void**)&H1,    g_H1);
    cudaGetSymbolAddress((void**)&Hm,    g_Hm);
    cudaGetSymbolAddress((void**)&WaT,   g_WaT);
    cudaGetSymbolAddress((void**)&Wbcat, g_Wbcat);

    // Weight repack + gating (independent of the FFN GEMMs, cheap)
    prep_kernel<<<(DD * NM + 255) / 256, 256>>>(Wa1, Wa2, (const float*)d_in[8], Wb2);
    gate_kernel<<<TT / 8, 256>>>(x, Wg1, Wg2);

    // FFN: out = gelu(x@W1 + b1) @ W2 + b2
    gemm_kernel<0><<<dim3(FF / 128, TT / 128), 256>>>(x,  W1, b1, H1,  TT, FF, DD, nullptr);
    gemm_kernel<1><<<dim3(DD / 128, TT / 128), 256>>>(H1, W2, b2, out, TT, DD, FF, nullptr);

    // MoE (both layers fused along N / K): only tokens with s >= id do real work
    gemm_kernel<2><<<dim3(NM / 128, TT / 128), 256>>>(x,  WaT,   nullptr, Hm,  TT, NM, DD, idp);
    gemm_kernel<3><<<dim3(DD / 128, TT / 128), 256>>>(Hm, Wbcat, nullptr, out, TT, DD, NM, idp);
}

// round 4
// speedup vs baseline: 3.1778x; 3.1778x over previous
#include <cuda_runtime.h>

#define TT 32768      // B*S tokens
#define SS 8192       // sequence length
#define DD 512        // model dim
#define FF 2048       // ffn hidden
#define NM 1024       // concatenated MoE hidden (2 layers * E*H)

#define BM 128
#define BN 128
#define BK 32
#define NSTG 3
#define PADW 36                            // floats per smem row (144B)
#define STG_FLOATS ((BM + BN) * PADW)      // 9216 floats per stage
#define SMEM_BYTES (NSTG * STG_FLOATS * 4) // 110592

// Scratch (device globals; no allocation allowed)
__device__ float g_H1[(unsigned long long)TT * FF];
__device__ float g_Hm[(unsigned long long)TT * NM];
__device__ float g_W1t[FF * DD];     // W1^T  [2048,512] K-major
__device__ float g_W2t[DD * FF];     // W2^T  [512,2048] K-major
__device__ float g_WaTt[NM * DD];    // MoE up weights [1024,512] K-major
__device__ float g_Wbt[DD * NM];     // MoE down weights [512,1024] K-major
__device__ float g_w[TT * 16];       // dense gate weights

__device__ __forceinline__ float gelu_f(float x) {
    float x3 = x * x * x;
    float t = tanhf(0.7978845608028654f * (x + 0.044715f * x3));
    return 0.5f * x * (1.0f + t);
}

__device__ __forceinline__ void cp16(unsigned dst, const void* src) {
    asm volatile("cp.async.cg.shared.global [%0], [%1], 16;" :: "r"(dst), "l"(src) : "memory");
}
__device__ __forceinline__ void cp_commit() {
    asm volatile("cp.async.commit_group;" ::: "memory");
}
__device__ __forceinline__ unsigned f2tf(unsigned u) {
    unsigned d;
    asm("cvt.rna.tf32.f32 %0, %1;" : "=r"(d) : "f"(__uint_as_float(u)));
    return d;
}
__device__ __forceinline__ void ldsm4(unsigned& r0, unsigned& r1, unsigned& r2, unsigned& r3,
                                      unsigned addr) {
    asm volatile("ldmatrix.sync.aligned.m8n8.x4.shared.b16 {%0,%1,%2,%3}, [%4];"
                 : "=r"(r0), "=r"(r1), "=r"(r2), "=r"(r3) : "r"(addr));
}
__device__ __forceinline__ void mma_tf32(float* c, const unsigned* a, const unsigned* b) {
    asm volatile(
        "mma.sync.aligned.m16n8k8.row.col.f32.tf32.tf32.f32 "
        "{%0,%1,%2,%3}, {%4,%5,%6,%7}, {%8,%9}, {%0,%1,%2,%3};"
        : "+f"(c[0]), "+f"(c[1]), "+f"(c[2]), "+f"(c[3])
        : "r"(a[0]), "r"(a[1]), "r"(a[2]), "r"(a[3]), "r"(b[0]), "r"(b[1]));
}

// ---------------------------------------------------------------------------
// Weight repacks (all outputs K-major [N, K])
// ---------------------------------------------------------------------------
__global__ void prep_w1(const float* __restrict__ W1) {      // [512,2048] -> [2048,512]
    int i = blockIdx.x * 256 + threadIdx.x;
    int n = i >> 9, d = i & 511;
    g_W1t[i] = W1[d * FF + n];
}
__global__ void prep_w2(const float* __restrict__ W2) {      // [2048,512] -> [512,2048]
    int i = blockIdx.x * 256 + threadIdx.x;
    int d = i >> 11, f = i & 2047;
    g_W2t[i] = W2[f * DD + d];
}
__global__ void prep_wa(const float* __restrict__ Wa1, const float* __restrict__ Wa2) {
    int i = blockIdx.x * 256 + threadIdx.x;                  // -> [1024,512]
    int n = i >> 9, d = i & 511;
    int L = n >> 9, c = n & 511;
    const float* Wa = L ? Wa2 : Wa1;                         // [E,D,H]
    g_WaTt[i] = Wa[((c >> 6) * DD + d) * 64 + (c & 63)];
}
__global__ void prep_wb(const float* __restrict__ Wb1, const float* __restrict__ Wb2) {
    int i = blockIdx.x * 256 + threadIdx.x;                  // -> [512,1024]
    int d = i >> 10, j = i & 1023;
    const float* Wb = (j >> 9) ? Wb2 : Wb1;                  // [E,H,D] flat [512,512]
    g_Wbt[i] = Wb[(j & 511) * DD + d];
}

// ---------------------------------------------------------------------------
// Gating: one warp per token
// ---------------------------------------------------------------------------
__device__ __forceinline__ void write_top2(const float* a, float* o) {
    int i0 = 0; float v0 = a[0];
#pragma unroll
    for (int e = 1; e < 8; e++) if (a[e] > v0) { v0 = a[e]; i0 = e; }
    int i1 = -1; float v1 = -3.4e38f;
#pragma unroll
    for (int e = 0; e < 8; e++) if (e != i0 && a[e] > v1) { v1 = a[e]; i1 = e; }
    float t = expf(v1 - v0);
    float inv = 1.0f / (1.0f + t);
#pragma unroll
    for (int e = 0; e < 8; e++) o[e] = 0.0f;
    o[i0] = inv;
    o[i1] = t * inv;
}

__global__ void gate_kernel(const float* __restrict__ x,
                            const float* __restrict__ Wg1,
                            const float* __restrict__ Wg2) {
    int tok = blockIdx.x * 8 + (threadIdx.x >> 5);
    int lane = threadIdx.x & 31;
    if (tok >= TT) return;
    const float* xr = x + (size_t)tok * DD;
    float a1[8], a2[8];
#pragma unroll
    for (int e = 0; e < 8; e++) { a1[e] = 0.0f; a2[e] = 0.0f; }
    for (int j = lane; j < DD; j += 32) {
        float xv = xr[j];
#pragma unroll
        for (int e = 0; e < 8; e++) {
            a1[e] = fmaf(xv, Wg1[j * 8 + e], a1[e]);
            a2[e] = fmaf(xv, Wg2[j * 8 + e], a2[e]);
        }
    }
#pragma unroll
    for (int e = 0; e < 8; e++) {
#pragma unroll
        for (int o = 16; o; o >>= 1) {
            a1[e] += __shfl_xor_sync(0xffffffffu, a1[e], o);
            a2[e] += __shfl_xor_sync(0xffffffffu, a2[e], o);
        }
    }
    if (lane == 0) {
        write_top2(a1, &g_w[tok * 16]);
        write_top2(a2, &g_w[tok * 16 + 8]);
    }
}

// ---------------------------------------------------------------------------
// tf32 mma.sync GEMM: 128x128 tile, BK=32, 3-stage cp.async pipeline.
// A [M,K] K-major, Bt [N,K] K-major. 8 warps, each a 64x32 sub-tile.
// EPI 0: C = gelu(acc + bias)      EPI 1: C = acc + bias
// EPI 2: C = mask * w * gelu(acc)  EPI 3: C += acc (rows s>=id)
// ---------------------------------------------------------------------------
template <int EPI>
__global__ __launch_bounds__(256, 2)
void gemm_mma(const float* __restrict__ A, const float* __restrict__ Bt,
              const float* __restrict__ bias, float* __restrict__ C,
              int K, int ldc, const int* __restrict__ idp)
{
    const int col0 = blockIdx.x * BN;
    const int row0 = blockIdx.y * BM;
    int idv = 0;
    if (EPI >= 2) {
        idv = *idp;
        if ((row0 & (SS - 1)) + BM - 1 < idv) return;   // tile fully masked
    }

    extern __shared__ float sm[];
    const unsigned smb = (unsigned)__cvta_generic_to_shared(sm);
    const int tid  = threadIdx.x;
    const int wid  = tid >> 5;
    const int lane = tid & 31;
    const int KT   = K >> 5;

    const int m0 = (wid >> 2) * 64;     // warp row offset in tile
    const int n0 = (wid & 3) * 32;      // warp col offset in tile

    // ldmatrix per-lane byte offsets (within a stage)
    const unsigned aoff = ((m0 + (lane & 7) + ((lane >> 3) & 1) * 8) * PADW
                           + (lane >> 4) * 4) * 4;
    const unsigned boff = ((BM + n0 + (lane & 7) + ((lane >> 3) & 2) * 4) * PADW
                           + ((lane >> 3) & 1) * 4) * 4;

    float acc[4][4][4];
#pragma unroll
    for (int i = 0; i < 4; i++)
#pragma unroll
        for (int j = 0; j < 4; j++)
#pragma unroll
            for (int r = 0; r < 4; r++) acc[i][j][r] = 0.0f;

    // ---- stage loader ----
    auto load_stage = [&](int st, int k0) {
        unsigned base = smb + (unsigned)(st * STG_FLOATS * 4);
#pragma unroll
        for (int i = 0; i < 8; i++) {
            int cid = tid + i * 256;
            int row = cid >> 3, c = cid & 7;
            unsigned dst = base + (unsigned)(row * PADW + c * 4) * 4;
            const float* src = (row < BM)
                ? A  + (size_t)(row0 + row) * K + k0 + c * 4
                : Bt + (size_t)(col0 + row - BM) * K + k0 + c * 4;
            cp16(dst, src);
        }
        cp_commit();
    };

    load_stage(0, 0);
    if (KT > 1) load_stage(1, BK);

#pragma unroll 1
    for (int kt = 0; kt < KT; kt++) {
        if (kt + 2 < KT) {
            load_stage((kt + 2) % NSTG, (kt + 2) * BK);
            asm volatile("cp.async.wait_group 2;" ::: "memory");
        } else if (kt + 1 < KT) {
            asm volatile("cp.async.wait_group 1;" ::: "memory");
        } else {
            asm volatile("cp.async.wait_group 0;" ::: "memory");
        }
        __syncthreads();

        const unsigned sbase = smb + (unsigned)((kt % NSTG) * STG_FLOATS * 4);
#pragma unroll
        for (int ks = 0; ks < 4; ks++) {
            const unsigned koff = ks * 32;     // 8 tf32 = 32B
            unsigned a[4][4];
#pragma unroll
            for (int mt = 0; mt < 4; mt++) {
                ldsm4(a[mt][0], a[mt][1], a[mt][2], a[mt][3],
                      sbase + aoff + (unsigned)(mt * 16 * PADW * 4) + koff);
                a[mt][0] = f2tf(a[mt][0]); a[mt][1] = f2tf(a[mt][1]);
                a[mt][2] = f2tf(a[mt][2]); a[mt][3] = f2tf(a[mt][3]);
            }
            unsigned b[4][2];
#pragma unroll
            for (int np = 0; np < 2; np++) {
                unsigned r0, r1, r2, r3;
                ldsm4(r0, r1, r2, r3,
                      sbase + boff + (unsigned)(np * 16 * PADW * 4) + koff);
                b[2*np][0]   = f2tf(r0); b[2*np][1]   = f2tf(r1);
                b[2*np+1][0] = f2tf(r2); b[2*np+1][1] = f2tf(r3);
            }
#pragma unroll
            for (int mt = 0; mt < 4; mt++)
#pragma unroll
                for (int nt = 0; nt < 4; nt++)
                    mma_tf32(acc[mt][nt], a[mt], b[nt]);
        }
        __syncthreads();
    }

    // ---- epilogue ----
    const int g = lane >> 2, t = lane & 3;
#pragma unroll
    for (int mt = 0; mt < 4; mt++) {
#pragma unroll
        for (int nt = 0; nt < 4; nt++) {
            int r0 = row0 + m0 + mt * 16 + g;
            int r1 = r0 + 8;
            int c  = col0 + n0 + nt * 8 + 2 * t;
            float* p0 = C + (size_t)r0 * ldc + c;
            float* p1 = C + (size_t)r1 * ldc + c;
            float v00 = acc[mt][nt][0], v01 = acc[mt][nt][1];
            float v10 = acc[mt][nt][2], v11 = acc[mt][nt][3];
            if (EPI == 0) {
                float2 bb = *(const float2*)(bias + c);
                float2 o0 = { gelu_f(v00 + bb.x), gelu_f(v01 + bb.y) };
                float2 o1 = { gelu_f(v10 + bb.x), gelu_f(v11 + bb.y) };
                *(float2*)p0 = o0; *(float2*)p1 = o1;
            } else if (EPI == 1) {
                float2 bb = *(const float2*)(bias + c);
                float2 o0 = { v00 + bb.x, v01 + bb.y };
                float2 o1 = { v10 + bb.x, v11 + bb.y };
                *(float2*)p0 = o0; *(float2*)p1 = o1;
            } else if (EPI == 2) {
                bool a0 = ((r0 & (SS - 1)) >= idv);
                bool a1 = ((r1 & (SS - 1)) >= idv);
                float w0 = a0 ? g_w[r0 * 16 + (c >> 6)] : 0.0f;
                float w1 = a1 ? g_w[r1 * 16 + (c >> 6)] : 0.0f;
                float2 o0 = { a0 ? gelu_f(v00) * w0 : 0.0f, a0 ? gelu_f(v01) * w0 : 0.0f };
                float2 o1 = { a1 ? gelu_f(v10) * w1 : 0.0f, a1 ? gelu_f(v11) * w1 : 0.0f };
                *(float2*)p0 = o0; *(float2*)p1 = o1;
            } else {  // EPI == 3
                if ((r0 & (SS - 1)) >= idv) {
                    float2 o = *(const float2*)p0;
                    o.x += v00; o.y += v01;
                    *(float2*)p0 = o;
                }
                if ((r1 & (SS - 1)) >= idv) {
                    float2 o = *(const float2*)p1;
                    o.x += v10; o.y += v11;
                    *(float2*)p1 = o;
                }
            }
        }
    }
}

// ---------------------------------------------------------------------------
extern "C" void kernel_launch(void* const* d_in, const int* in_sizes, int n_in,
                              void* d_out, int out_size) {
    const float* x   = (const float*)d_in[0];
    const int*   idp = (const int*)  d_in[1];
    const float* W1  = (const float*)d_in[2];
    const float* b1  = (const float*)d_in[3];
    const float* W2  = (const float*)d_in[4];
    const float* b2  = (const float*)d_in[5];
    const float* Wg1 = (const float*)d_in[6];
    const float* Wa1 = (const float*)d_in[7];
    const float* Wb1 = (const float*)d_in[8];
    const float* Wg2 = (const float*)d_in[9];
    const float* Wa2 = (const float*)d_in[10];
    const float* Wb2 = (const float*)d_in[11];
    float* out = (float*)d_out;
    (void)in_sizes; (void)n_in; (void)out_size;

    float *H1, *Hm, *W1t, *W2t, *WaTt, *Wbt;
    cudaGetSymbolAddress((void**)&H1,   g_H1);
    cudaGetSymbolAddress((void**)&Hm,   g_Hm);
    cudaGetSymbolAddress((void**)&W1t,  g_W1t);
    cudaGetSymbolAddress((void**)&W2t,  g_W2t);
    cudaGetSymbolAddress((void**)&WaTt, g_WaTt);
    cudaGetSymbolAddress((void**)&Wbt,  g_Wbt);

    cudaFuncSetAttribute(gemm_mma<0>, cudaFuncAttributeMaxDynamicSharedMemorySize, SMEM_BYTES);
    cudaFuncSetAttribute(gemm_mma<1>, cudaFuncAttributeMaxDynamicSharedMemorySize, SMEM_BYTES);
    cudaFuncSetAttribute(gemm_mma<2>, cudaFuncAttributeMaxDynamicSharedMemorySize, SMEM_BYTES);
    cudaFuncSetAttribute(gemm_mma<3>, cudaFuncAttributeMaxDynamicSharedMemorySize, SMEM_BYTES);

    // Weight repack + gating
    prep_w1<<<FF * DD / 256, 256>>>(W1);
    prep_w2<<<DD * FF / 256, 256>>>(W2);
    prep_wa<<<NM * DD / 256, 256>>>(Wa1, Wa2);
    prep_wb<<<DD * NM / 256, 256>>>(Wb1, Wb2);
    gate_kernel<<<TT / 8, 256>>>(x, Wg1, Wg2);

    // FFN: out = gelu(x@W1 + b1) @ W2 + b2
    gemm_mma<0><<<dim3(FF / BN, TT / BM), 256, SMEM_BYTES>>>(x,  W1t, b1, H1,  DD, FF, nullptr);
    gemm_mma<1><<<dim3(DD / BN, TT / BM), 256, SMEM_BYTES>>>(H1, W2t, b2, out, FF, DD, nullptr);

    // MoE (both layers fused): only tokens with s >= id do real work
    gemm_mma<2><<<dim3(NM / BN, TT / BM), 256, SMEM_BYTES>>>(x,  WaTt, nullptr, Hm,  DD, NM, idp);
    gemm_mma<3><<<dim3(DD / BN, TT / BM), 256, SMEM_BYTES>>>(Hm, Wbt,  nullptr, out, NM, DD, idp);
}